// round 15
// baseline (speedup 1.0000x reference)
#include <cuda_runtime.h>
#include <cuda_fp16.h>
#include <math.h>
#include <cstdint>

#define NN 16384
#define DD 512
#define OO 512
#define BM 128
#define BN 64
#define BK 64                   // k-tile (elements)
#define NKT (DD / BK)           // 8 k-tiles
#define ROWB 144                // bytes per smem fp16 row (128 + 16 pad)
#define XTB (BM * ROWB)         // 18432 B  X fp16 tile
#define CTB (BN * ROWB)         // 9216 B   C fp16 tile
#define BUFB (XTB + CTB)        // 27648 B per buffer
#define SM_X2 (2 * BUFB)        // 55296: x2 partials after the two buffers
#define SMEM_BYTES (SM_X2 + 256 * 4)   // 56320 B -> 2+ CTAs/SM
#define MINN 1e-15f

// Precomputed per-column stats + fp16 C operand (no allocations -> globals).
__device__ float g_paq[OO];   // <p,a> / (B * ||a||)   (B = 1-||p||^2 in fp64)
__device__ float g_e2[OO];    // ln(2) * exp(scale)
__device__ __half g_Ch[OO * DD];   // c = a/||a|| + 2*paq*p

__device__ __forceinline__ float warp_sum(float v) {
#pragma unroll
    for (int s = 16; s > 0; s >>= 1) v += __shfl_xor_sync(0xffffffffu, v, s);
    return v;
}
__device__ __forceinline__ double warp_sum_d(double v) {
#pragma unroll
    for (int s = 16; s > 0; s >>= 1) v += __shfl_xor_sync(0xffffffffu, v, s);
    return v;
}
__device__ __forceinline__ uint2 cvt4(float4 v) {
    __half2 h0 = __floats2half2_rn(v.x, v.y);
    __half2 h1 = __floats2half2_rn(v.z, v.w);
    uint2 u;
    u.x = *reinterpret_cast<uint32_t*>(&h0);
    u.y = *reinterpret_cast<uint32_t*>(&h1);
    return u;
}

// ---------------- o-prep: stats (B in fp64) + build fp16 c, one block per o --
__global__ void prep_o(const float* __restrict__ P, const float* __restrict__ A,
                       const float* __restrict__ S) {
    int o = blockIdx.x;
    int tid = threadIdx.x;        // 128 threads
    int wid = tid >> 5, lane = tid & 31;
    __shared__ double sp2[4];
    __shared__ float spa[4], sa2[4];
    __shared__ float sh_paq2, sh_ran;
    const float4* p4 = reinterpret_cast<const float4*>(P + (size_t)o * DD);
    const float4* a4 = reinterpret_cast<const float4*>(A + (size_t)o * DD);
    float4 pv = p4[tid];
    float4 av = a4[tid];
    double p2 = (double)pv.x * pv.x + (double)pv.y * pv.y +
                (double)pv.z * pv.z + (double)pv.w * pv.w;
    float pa = pv.x * av.x + pv.y * av.y + pv.z * av.z + pv.w * av.w;
    float a2 = av.x * av.x + av.y * av.y + av.z * av.z + av.w * av.w;
    p2 = warp_sum_d(p2);
    pa = warp_sum(pa);
    a2 = warp_sum(a2);
    if (lane == 0) { sp2[wid] = p2; spa[wid] = pa; sa2[wid] = a2; }
    __syncthreads();
    if (tid == 0) {
        double tp2 = sp2[0] + sp2[1] + sp2[2] + sp2[3];
        double tpa = (double)spa[0] + spa[1] + spa[2] + spa[3];
        double ta2 = (double)sa2[0] + sa2[1] + sa2[2] + sa2[3];
        double B = 1.0 - tp2;    // catastrophic cancellation handled in fp64
        double an = sqrt(ta2);
        if (an < (double)MINN) an = (double)MINN;
        double paq = tpa / (B * an);
        g_paq[o] = (float)paq;
        g_e2[o] = 0.69314718055994530942f * expf(S[o]);
        sh_paq2 = (float)(2.0 * paq);
        sh_ran = (float)(1.0 / an);
    }
    __syncthreads();
    float paq2 = sh_paq2, ran = sh_ran;
    float4 c;
    c.x = fmaf(paq2, pv.x, av.x * ran);
    c.y = fmaf(paq2, pv.y, av.y * ran);
    c.z = fmaf(paq2, pv.z, av.z * ran);
    c.w = fmaf(paq2, pv.w, av.w * ran);
    reinterpret_cast<uint2*>(g_Ch + (size_t)o * DD)[tid] = cvt4(c);
}

// ---------------- PTX helpers ----------------
#define MMA_F16(d, a, b0, b1)                                                  \
    asm volatile(                                                              \
        "mma.sync.aligned.m16n8k16.row.col.f32.f16.f16.f32 "                   \
        "{%0,%1,%2,%3}, {%4,%5,%6,%7}, {%8,%9}, {%0,%1,%2,%3};"                \
        : "+f"((d)[0]), "+f"((d)[1]), "+f"((d)[2]), "+f"((d)[3])               \
        : "r"((a)[0]), "r"((a)[1]), "r"((a)[2]), "r"((a)[3]), "r"(b0), "r"(b1))

#define LDMX4(r, addr)                                                         \
    asm volatile("ldmatrix.sync.aligned.m8n8.x4.shared.b16 {%0,%1,%2,%3}, [%4];" \
                 : "=r"((r)[0]), "=r"((r)[1]), "=r"((r)[2]), "=r"((r)[3])      \
                 : "r"(addr))

#define CPA16(saddr, gptr)                                                     \
    asm volatile("cp.async.cg.shared.global [%0], [%1], 16;"                   \
                 :: "r"(saddr), "l"(gptr))
#define CPA_COMMIT() asm volatile("cp.async.commit_group;" ::: "memory")
#define CPA_WAIT0() asm volatile("cp.async.wait_group 0;" ::: "memory")

// asinh(arg)*e^s: asinh t = ln(t+sqrt(t^2+1)) = lg2(.)*ln2.
// Fast path (warp-uniform): all lanes |t| >= 64 -> asinh(t) ~= ln(2t).
__device__ __forceinline__ float epi(float xc, float a0, float rr,
                                     float paq, float e2) {
    float arg = (xc - a0 * paq) * rr;
    float tt = fabsf(arg);
    float u;
    if (__any_sync(0xffffffffu, tt < 64.f)) {
        float s;
        asm("sqrt.approx.f32 %0, %1;" : "=f"(s) : "f"(fmaf(tt, tt, 1.f)));
        u = tt + s;
    } else {
        u = tt + tt;
    }
    float r;
    asm("lg2.approx.f32 %0, %1;" : "=f"(r) : "f"(u));
    return copysignf(r * e2, arg);
}

// ---------------- main: fused X fp32->fp16 convert + fp16 GEMM + epilogue ----
// 128x64 block tile, 256 threads, warp grid 2(M) x 4(N), warp tile 64x16.
// X loaded as fp32 via LDG (register-pipelined), converted + STS'd to fp16;
// per-half-row ||x||^2 accumulated in flight. C via cp.async (fp16, distance 1).
__global__ void __launch_bounds__(256, 2) mobius_main(const float* __restrict__ X,
                                                      float* __restrict__ out) {
    extern __shared__ char smc[];
    int tid = threadIdx.x;
    int lane = tid & 31, wid = tid >> 5;
    int wm = wid & 1, wn = wid >> 1;
    int m0 = blockIdx.y * BM, n0 = blockIdx.x * BN;
    uint32_t sb = (uint32_t)__cvta_generic_to_shared(smc);
    float* x2p = reinterpret_cast<float*>(smc + SM_X2);

    // X loader mapping: thread -> (row, half); half-row = 32 fp32 = 8 float4
    int r = tid >> 1, h = tid & 1;
    const float4* xg =
        reinterpret_cast<const float4*>(X + (size_t)(m0 + r) * DD) + h * 8;
    uint32_t xsts = sb + (uint32_t)(r * ROWB + h * 64);
    const char* Cg = reinterpret_cast<const char*>(g_Ch) + (size_t)n0 * (DD * 2);

    float4 xv[8];
    float x2acc = 0.f;

#define XLDG(kt)                                                               \
    { _Pragma("unroll") for (int j = 0; j < 8; j++) xv[j] = xg[(kt) * 16 + j]; }

#define XSTS(buf)                                                              \
    {                                                                          \
        uint32_t d = xsts + (uint32_t)(buf) * BUFB;                            \
        _Pragma("unroll") for (int j = 0; j < 8; j++) {                        \
            uint2 q = cvt4(xv[j]);                                             \
            asm volatile("st.shared.v2.u32 [%0], {%1,%2};"                     \
                         :: "r"(d + j * 8), "r"(q.x), "r"(q.y));               \
            x2acc += xv[j].x * xv[j].x + xv[j].y * xv[j].y +                   \
                     xv[j].z * xv[j].z + xv[j].w * xv[j].w;                    \
        }                                                                      \
    }

#define CLOAD(buf, kt)                                                         \
    {                                                                          \
        uint32_t cb = sb + (uint32_t)(buf) * BUFB + XTB;                       \
        _Pragma("unroll") for (int j = 0; j < 2; j++) {                        \
            int f = tid + 256 * j;                                             \
            int row = f >> 3, ck = f & 7;                                      \
            CPA16(cb + (uint32_t)(row * ROWB + ck * 16),                       \
                  Cg + (size_t)row * (DD * 2) + (kt) * 128 + ck * 16);         \
        }                                                                      \
    }

    float acc[4][2][4];
#pragma unroll
    for (int mt = 0; mt < 4; mt++)
#pragma unroll
        for (int nt = 0; nt < 2; nt++)
#pragma unroll
            for (int e = 0; e < 4; e++) acc[mt][nt][e] = 0.f;

    // prologue: tile 0 staged, tile 1 X in regs
    XLDG(0);
    CLOAD(0, 0); CPA_COMMIT();
    XSTS(0);
    XLDG(1);

    // ldmatrix per-lane base addresses (bytes, within a buffer)
    uint32_t a_base = (uint32_t)((wm * 64 + (lane & 15)) * ROWB + ((lane >> 4) << 4));
    uint32_t b_row = (uint32_t)(wn * 16 + (((lane >> 4) & 1) << 3) + (lane & 7));
    uint32_t b_base = (uint32_t)(b_row * ROWB + (((lane >> 3) & 1) << 4));

    for (int c = 0; c < NKT; ++c) {
        CPA_WAIT0();
        __syncthreads();
        if (c + 1 < NKT) { CLOAD((c + 1) & 1, c + 1); }
        CPA_COMMIT();
        if (c + 1 < NKT) { XSTS((c + 1) & 1); }
        if (c + 2 < NKT) { XLDG(c + 2); }

        uint32_t st = sb + (uint32_t)(c & 1) * BUFB;
        uint32_t aA = st + a_base;
        uint32_t aC = st + XTB + b_base;
#pragma unroll
        for (int ks = 0; ks < 4; ks++) {    // 4 x k16 per k-tile of 64
            uint32_t af[4][4], bc[4];
#pragma unroll
            for (int mt = 0; mt < 4; mt++)
                LDMX4(af[mt], aA + (uint32_t)(mt * 16 * ROWB + ks * 32));
            LDMX4(bc, aC + (uint32_t)(ks * 32));
#pragma unroll
            for (int nt = 0; nt < 2; nt++) {
#pragma unroll
                for (int mt = 0; mt < 4; mt++)
                    MMA_F16(acc[mt][nt], af[mt], bc[2 * nt], bc[2 * nt + 1]);
            }
        }
    }

    x2p[tid] = x2acc;
    __syncthreads();

    // ---- epilogue: a0/rr from x2 partials; arg = (xc - a0*paq)*rr ----
    int g = lane >> 2, t = lane & 3;
    float a0r[4][2], rrr[4][2];
#pragma unroll
    for (int mt = 0; mt < 4; mt++)
#pragma unroll
        for (int h2 = 0; h2 < 2; h2++) {
            int rl = wm * 64 + mt * 16 + g + h2 * 8;
            float x2 = x2p[2 * rl] + x2p[2 * rl + 1];
            a0r[mt][h2] = 1.f + x2;
            rrr[mt][h2] = 2.f / (1.f - x2);
        }
    float paqc[2][2], e2c[2][2];
#pragma unroll
    for (int nt = 0; nt < 2; nt++)
#pragma unroll
        for (int w = 0; w < 2; w++) {
            int cc = n0 + wn * 16 + nt * 8 + 2 * t + w;
            paqc[nt][w] = g_paq[cc];
            e2c[nt][w] = g_e2[cc];
        }
#pragma unroll
    for (int mt = 0; mt < 4; mt++) {
#pragma unroll
        for (int h2 = 0; h2 < 2; h2++) {
            int row = m0 + wm * 64 + mt * 16 + g + h2 * 8;
            float* orow = out + (size_t)row * OO + n0 + wn * 16 + 2 * t;
#pragma unroll
            for (int nt = 0; nt < 2; nt++) {
                float o0 = epi(acc[mt][nt][h2 * 2 + 0], a0r[mt][h2], rrr[mt][h2],
                               paqc[nt][0], e2c[nt][0]);
                float o1 = epi(acc[mt][nt][h2 * 2 + 1], a0r[mt][h2], rrr[mt][h2],
                               paqc[nt][1], e2c[nt][1]);
                *reinterpret_cast<float2*>(orow + nt * 8) = make_float2(o0, o1);
            }
        }
    }
}

extern "C" void kernel_launch(void* const* d_in, const int* in_sizes, int n_in,
                              void* d_out, int out_size) {
    const float* x = (const float*)d_in[0];      // [N, D]
    const float* p = (const float*)d_in[1];      // [O, D]
    const float* a = (const float*)d_in[2];      // [O, D]
    const float* s = (const float*)d_in[3];      // [O]
    float* out = (float*)d_out;                  // [N, O]

    prep_o<<<OO, 128>>>(p, a, s);
    cudaFuncSetAttribute(mobius_main, cudaFuncAttributeMaxDynamicSharedMemorySize,
                         SMEM_BYTES);
    dim3 grid(OO / BN, NN / BM);
    mobius_main<<<grid, 256, SMEM_BYTES>>>(x, out);
}

// round 17
// speedup vs baseline: 2.1334x; 2.1334x over previous
#include <cuda_runtime.h>
#include <cuda_fp16.h>
#include <math.h>
#include <cstdint>

#define NN 16384
#define DD 512
#define OO 512
#define BM 128
#define BN 64
#define BK 64                   // k-tile in elements (fp16)
#define NKT (DD / BK)           // 8 k-tiles
#define LH 72                   // smem fp16 per row (144B) -> conflict-free ldmatrix
#define TXH (BM * LH)           // 9216 halfs, X tile
#define TCH (BN * LH)           // 4608 halfs, C tile
#define STAGE_H (TXH + TCH)     // 13824 halfs = 27648 B
#define SMEM_BYTES (2 * STAGE_H * 2)  // 55296 B, 2 stages -> 3 CTAs/SM
#define MINN 1e-15f

// Precomputed stats + fp16 operands (no allocations -> device globals).
__device__ float g_a0[NN];    // 1 + ||x||^2
__device__ float g_rr[NN];    // 2 / (1 - ||x||^2)
__device__ float g_paq[OO];   // <p,a> / (B * ||a||)   (B = 1-||p||^2 in fp64)
__device__ float g_e2[OO];    // ln(2) * exp(scale)
__device__ __half g_Xh[NN * DD];
__device__ __half g_Ch[OO * DD];   // c = a/||a|| + 2*paq*p

__device__ __forceinline__ float warp_sum(float v) {
#pragma unroll
    for (int s = 16; s > 0; s >>= 1) v += __shfl_xor_sync(0xffffffffu, v, s);
    return v;
}
__device__ __forceinline__ double warp_sum_d(double v) {
#pragma unroll
    for (int s = 16; s > 0; s >>= 1) v += __shfl_xor_sync(0xffffffffu, v, s);
    return v;
}
__device__ __forceinline__ uint2 cvt4(float4 v) {
    __half2 h0 = __floats2half2_rn(v.x, v.y);
    __half2 h1 = __floats2half2_rn(v.z, v.w);
    uint2 u;
    u.x = *reinterpret_cast<uint32_t*>(&h0);
    u.y = *reinterpret_cast<uint32_t*>(&h1);
    return u;
}

// ---------------- fused prep ----------------
// blocks [0, 1024): X convert + x-stats, 2 rows per warp, MLP 8.
// blocks [1024, 1536): one block per o: stats (B fp64) + build fp16 c.
__global__ void prep(const float* __restrict__ X, const float* __restrict__ P,
                     const float* __restrict__ A, const float* __restrict__ S) {
    int bid = blockIdx.x;
    int tid = threadIdx.x;
    int wid = tid >> 5, lane = tid & 31;
    if (bid < 1024) {
        int r0 = bid * 16 + wid * 2;
        const float4* x40 = reinterpret_cast<const float4*>(X + (size_t)r0 * DD);
        const float4* x41 = reinterpret_cast<const float4*>(X + (size_t)(r0 + 1) * DD);
        uint2* xh0 = reinterpret_cast<uint2*>(g_Xh + (size_t)r0 * DD);
        uint2* xh1 = reinterpret_cast<uint2*>(g_Xh + (size_t)(r0 + 1) * DD);
        float4 v0[4], v1[4];
#pragma unroll
        for (int j = 0; j < 4; j++) v0[j] = x40[lane + 32 * j];
#pragma unroll
        for (int j = 0; j < 4; j++) v1[j] = x41[lane + 32 * j];
        float s0 = 0.f, s1 = 0.f;
#pragma unroll
        for (int j = 0; j < 4; j++) {
            xh0[lane + 32 * j] = cvt4(v0[j]);
            xh1[lane + 32 * j] = cvt4(v1[j]);
            s0 += v0[j].x * v0[j].x + v0[j].y * v0[j].y +
                  v0[j].z * v0[j].z + v0[j].w * v0[j].w;
            s1 += v1[j].x * v1[j].x + v1[j].y * v1[j].y +
                  v1[j].z * v1[j].z + v1[j].w * v1[j].w;
        }
        s0 = warp_sum(s0);
        s1 = warp_sum(s1);
        if (lane == 0) {
            g_a0[r0] = 1.f + s0;
            g_rr[r0] = 2.f / (1.f - s0);
            g_a0[r0 + 1] = 1.f + s1;
            g_rr[r0 + 1] = 2.f / (1.f - s1);
        }
    } else {
        int o = bid - 1024;
        __shared__ double sp2[4];
        __shared__ float spa[4], sa2[4];
        __shared__ float sh_paq2, sh_ran;
        float4 pv, av;
        if (tid < 128) {
            const float4* p4 = reinterpret_cast<const float4*>(P + (size_t)o * DD);
            const float4* a4 = reinterpret_cast<const float4*>(A + (size_t)o * DD);
            pv = p4[tid];
            av = a4[tid];
            double p2 = (double)pv.x * pv.x + (double)pv.y * pv.y +
                        (double)pv.z * pv.z + (double)pv.w * pv.w;
            float pa = pv.x * av.x + pv.y * av.y + pv.z * av.z + pv.w * av.w;
            float a2 = av.x * av.x + av.y * av.y + av.z * av.z + av.w * av.w;
            p2 = warp_sum_d(p2);
            pa = warp_sum(pa);
            a2 = warp_sum(a2);
            if (lane == 0) { sp2[wid] = p2; spa[wid] = pa; sa2[wid] = a2; }
        }
        __syncthreads();
        if (tid == 0) {
            double tp2 = sp2[0] + sp2[1] + sp2[2] + sp2[3];
            double tpa = (double)spa[0] + spa[1] + spa[2] + spa[3];
            double ta2 = (double)sa2[0] + sa2[1] + sa2[2] + sa2[3];
            double B = 1.0 - tp2;    // catastrophic cancellation handled in fp64
            double an = sqrt(ta2);
            if (an < (double)MINN) an = (double)MINN;
            double paq = tpa / (B * an);
            g_paq[o] = (float)paq;
            g_e2[o] = 0.69314718055994530942f * expf(S[o]);
            sh_paq2 = (float)(2.0 * paq);
            sh_ran = (float)(1.0 / an);
        }
        __syncthreads();
        if (tid < 128) {
            float paq2 = sh_paq2, ran = sh_ran;
            float4 c;
            c.x = fmaf(paq2, pv.x, av.x * ran);
            c.y = fmaf(paq2, pv.y, av.y * ran);
            c.z = fmaf(paq2, pv.z, av.z * ran);
            c.w = fmaf(paq2, pv.w, av.w * ran);
            reinterpret_cast<uint2*>(g_Ch + (size_t)o * DD)[tid] = cvt4(c);
        }
    }
}

// ---------------- PTX helpers ----------------
#define MMA_F16(d, a, b0, b1)                                                  \
    asm volatile(                                                              \
        "mma.sync.aligned.m16n8k16.row.col.f32.f16.f16.f32 "                   \
        "{%0,%1,%2,%3}, {%4,%5,%6,%7}, {%8,%9}, {%0,%1,%2,%3};"                \
        : "+f"((d)[0]), "+f"((d)[1]), "+f"((d)[2]), "+f"((d)[3])               \
        : "r"((a)[0]), "r"((a)[1]), "r"((a)[2]), "r"((a)[3]), "r"(b0), "r"(b1))

#define LDMX4(r, addr)                                                         \
    asm volatile("ldmatrix.sync.aligned.m8n8.x4.shared.b16 {%0,%1,%2,%3}, [%4];" \
                 : "=r"((r)[0]), "=r"((r)[1]), "=r"((r)[2]), "=r"((r)[3])      \
                 : "r"(addr))

#define CPA16(saddr, gptr)                                                     \
    asm volatile("cp.async.cg.shared.global [%0], [%1], 16;"                   \
                 :: "r"(saddr), "l"(gptr))
#define CPA_COMMIT() asm volatile("cp.async.commit_group;" ::: "memory")
#define CPA_WAIT0() asm volatile("cp.async.wait_group 0;" ::: "memory")

// asinh(arg)*e^s: asinh t = ln(t+sqrt(t^2+1)) = lg2(.)*ln2.
// Fast path (warp-uniform): all lanes |t| >= 64 -> asinh(t) ~= ln(2t).
__device__ __forceinline__ float epi(float xc, float a0, float rr,
                                     float paq, float e2) {
    float arg = (xc - a0 * paq) * rr;
    float tt = fabsf(arg);
    float u;
    if (__any_sync(0xffffffffu, tt < 64.f)) {
        float s;
        asm("sqrt.approx.f32 %0, %1;" : "=f"(s) : "f"(fmaf(tt, tt, 1.f)));
        u = tt + s;
    } else {
        u = tt + tt;
    }
    float r;
    asm("lg2.approx.f32 %0, %1;" : "=f"(r) : "f"(u));
    return copysignf(r * e2, arg);
}

// ---------------- main: single fp16 GEMM (x @ c^T) + tiny epilogue -----------
// 128x64 block tile, 256 threads, warp grid 2(M) x 4(N), warp tile 64x16.
// 2-stage cp.async pipeline (distance 1, load-before-compute, one barrier),
// 3 CTAs/SM (24 warps) for latency hiding; grid 1024.
__global__ void __launch_bounds__(256, 3) mobius_main(float* __restrict__ out) {
    extern __shared__ __half smh[];
    int tid = threadIdx.x;
    int lane = tid & 31, wid = tid >> 5;
    int wm = wid & 1, wn = wid >> 1;
    int m0 = blockIdx.y * BM, n0 = blockIdx.x * BN;

    const __half* Xg = g_Xh + (size_t)m0 * DD;
    const __half* Cg = g_Ch + (size_t)n0 * DD;
    uint32_t sbase = (uint32_t)__cvta_generic_to_shared(smh);

#define LOAD_STAGE(stg, kt)                                                    \
    {                                                                          \
        uint32_t st = sbase + (uint32_t)(stg) * (STAGE_H * 2);                 \
        int k0 = (kt) * BK;                                                    \
        _Pragma("unroll") for (int j = 0; j < 4; j++) {  /* X: 1024 chunks */  \
            int f = tid + 256 * j;                                             \
            int row = f >> 3, ck = f & 7;                                      \
            CPA16(st + (uint32_t)(row * (LH * 2) + ck * 16),                   \
                  Xg + (size_t)row * DD + k0 + ck * 8);                        \
        }                                                                      \
        _Pragma("unroll") for (int j = 0; j < 2; j++) {  /* C: 512 chunks */   \
            int f = tid + 256 * j;                                             \
            int row = f >> 3, ck = f & 7;                                      \
            CPA16(st + (uint32_t)(TXH * 2 + row * (LH * 2) + ck * 16),         \
                  Cg + (size_t)row * DD + k0 + ck * 8);                        \
        }                                                                      \
    }

    float acc[4][2][4];
#pragma unroll
    for (int mt = 0; mt < 4; mt++)
#pragma unroll
        for (int nt = 0; nt < 2; nt++)
#pragma unroll
            for (int e = 0; e < 4; e++) acc[mt][nt][e] = 0.f;

    LOAD_STAGE(0, 0); CPA_COMMIT();

    // ldmatrix per-lane base addresses (bytes, within a stage)
    uint32_t a_base = (uint32_t)(((wm * 64 + (lane & 15)) * LH + ((lane >> 4) << 3)) * 2);
    uint32_t b_row = (uint32_t)(wn * 16 + (((lane >> 4) & 1) << 3) + (lane & 7));
    uint32_t b_base = (uint32_t)((b_row * LH + (((lane >> 3) & 1) << 3)) * 2);

    for (int c = 0; c < NKT; ++c) {
        CPA_WAIT0();
        __syncthreads();
        if (c + 1 < NKT) { LOAD_STAGE((c + 1) & 1, c + 1); }
        CPA_COMMIT();

        uint32_t st = sbase + (uint32_t)(c & 1) * (STAGE_H * 2);
        uint32_t aA = st + a_base;
        uint32_t aC = st + TXH * 2 + b_base;
#pragma unroll
        for (int ks = 0; ks < 4; ks++) {    // 4 x k16 per k-tile of 64
            uint32_t af[4][4], bc[4];
#pragma unroll
            for (int mt = 0; mt < 4; mt++)
                LDMX4(af[mt], aA + (uint32_t)(mt * 16 * LH * 2 + ks * 32));
            LDMX4(bc, aC + (uint32_t)(ks * 32));
#pragma unroll
            for (int nt = 0; nt < 2; nt++) {
#pragma unroll
                for (int mt = 0; mt < 4; mt++)
                    MMA_F16(acc[mt][nt], af[mt], bc[2 * nt], bc[2 * nt + 1]);
            }
        }
    }

    // ---- epilogue: arg = (xc - a0*paq)*rr; dist = asinh(arg)*e^s ----
    int g = lane >> 2, t = lane & 3;
    float a0r[4][2], rrr[4][2];
#pragma unroll
    for (int mt = 0; mt < 4; mt++)
#pragma unroll
        for (int h = 0; h < 2; h++) {
            int r = m0 + wm * 64 + mt * 16 + g + h * 8;
            a0r[mt][h] = g_a0[r];
            rrr[mt][h] = g_rr[r];
        }
    float paqc[2][2], e2c[2][2];
#pragma unroll
    for (int nt = 0; nt < 2; nt++)
#pragma unroll
        for (int w = 0; w < 2; w++) {
            int cc = n0 + wn * 16 + nt * 8 + 2 * t + w;
            paqc[nt][w] = g_paq[cc];
            e2c[nt][w] = g_e2[cc];
        }
#pragma unroll
    for (int mt = 0; mt < 4; mt++) {
#pragma unroll
        for (int h = 0; h < 2; h++) {
            int r = m0 + wm * 64 + mt * 16 + g + h * 8;
            float* orow = out + (size_t)r * OO + n0 + wn * 16 + 2 * t;
#pragma unroll
            for (int nt = 0; nt < 2; nt++) {
                float o0 = epi(acc[mt][nt][h * 2 + 0], a0r[mt][h], rrr[mt][h],
                               paqc[nt][0], e2c[nt][0]);
                float o1 = epi(acc[mt][nt][h * 2 + 1], a0r[mt][h], rrr[mt][h],
                               paqc[nt][1], e2c[nt][1]);
                *reinterpret_cast<float2*>(orow + nt * 8) = make_float2(o0, o1);
            }
        }
    }
}

extern "C" void kernel_launch(void* const* d_in, const int* in_sizes, int n_in,
                              void* d_out, int out_size) {
    const float* x = (const float*)d_in[0];      // [N, D]
    const float* p = (const float*)d_in[1];      // [O, D]
    const float* a = (const float*)d_in[2];      // [O, D]
    const float* s = (const float*)d_in[3];      // [O]
    float* out = (float*)d_out;                  // [N, O]

    prep<<<1024 + OO, 256>>>(x, p, a, s);
    cudaFuncSetAttribute(mobius_main, cudaFuncAttributeMaxDynamicSharedMemorySize,
                         SMEM_BYTES);
    dim3 grid(OO / BN, NN / BM);
    mobius_main<<<grid, 256, SMEM_BYTES>>>(out);
}